// round 1
// baseline (speedup 1.0000x reference)
#include <cuda_runtime.h>
#include <math.h>

#define D_MODEL 1024
#define FF_DIM  4096
#define BATCH   4
#define SEQ     1024
#define HEADS   16
#define HDIM    64
#define ROWS    (BATCH*SEQ)   // 4096

// ---------------- scratch (static device arrays; no allocation) ----------------
__device__ float g_qkin[ROWS*D_MODEL];
__device__ float g_Q   [ROWS*D_MODEL];
__device__ float g_K   [ROWS*D_MODEL];
__device__ float g_V   [ROWS*D_MODEL];
__device__ float g_attn[ROWS*D_MODEL];
__device__ float g_x1  [ROWS*D_MODEL];
__device__ float g_ff1 [ROWS*FF_DIM];
__device__ float g_h   [ROWS*D_MODEL];

// ---------------- elementwise add (qk_in = input + pos) ----------------
__global__ __launch_bounds__(256) void add_kernel(const float* __restrict__ a,
                                                  const float* __restrict__ b,
                                                  float* __restrict__ c, int n4)
{
    int i = blockIdx.x * blockDim.x + threadIdx.x;
    if (i < n4) {
        float4 x = ((const float4*)a)[i];
        float4 y = ((const float4*)b)[i];
        x.x += y.x; x.y += y.y; x.z += y.z; x.w += y.w;
        ((float4*)c)[i] = x;
    }
}

// ---------------- SGEMM: C[M,N] = A[M,K] @ B[K,N] (+epilogue) ----------------
// EPI: 0 = none, 1 = +bias then relu, 2 = +bias +residual
// BM=BN=128, BK=8, 256 threads, 8x8 register tile per thread.
template<int EPI>
__global__ __launch_bounds__(256) void sgemm_kernel(const float* __restrict__ A,
                                                    const float* __restrict__ B,
                                                    const float* __restrict__ bias,
                                                    const float* __restrict__ res,
                                                    float* __restrict__ C,
                                                    int M, int N, int K)
{
    __shared__ float As[8][128];
    __shared__ float Bs[8][128];

    const int tid  = threadIdx.x;
    const int brow = blockIdx.y * 128;
    const int bcol = blockIdx.x * 128;
    const int tr   = (tid >> 4) * 8;     // 0..120
    const int tc   = (tid & 15) * 8;     // 0..120
    const int rowA = tid >> 1;           // 0..127
    const int colA = (tid & 1) * 4;      // 0 or 4
    const int rowB = tid >> 5;           // 0..7
    const int colB = (tid & 31) * 4;     // 0..124

    float acc[8][8];
    #pragma unroll
    for (int i = 0; i < 8; i++)
        #pragma unroll
        for (int j = 0; j < 8; j++) acc[i][j] = 0.f;

    const float* Ap = A + (size_t)(brow + rowA) * K + colA;
    const float* Bp = B + (size_t)rowB * N + bcol + colB;

    for (int k0 = 0; k0 < K; k0 += 8) {
        float4 a4 = *(const float4*)(Ap + k0);
        float4 b4 = *(const float4*)(Bp + (size_t)k0 * N);
        As[colA + 0][rowA] = a4.x;
        As[colA + 1][rowA] = a4.y;
        As[colA + 2][rowA] = a4.z;
        As[colA + 3][rowA] = a4.w;
        *(float4*)&Bs[rowB][colB] = b4;
        __syncthreads();

        #pragma unroll
        for (int k = 0; k < 8; k++) {
            float4 a0 = *(float4*)&As[k][tr];
            float4 a1 = *(float4*)&As[k][tr + 4];
            float4 b0 = *(float4*)&Bs[k][tc];
            float4 b1 = *(float4*)&Bs[k][tc + 4];
            float ra[8] = {a0.x, a0.y, a0.z, a0.w, a1.x, a1.y, a1.z, a1.w};
            float rb[8] = {b0.x, b0.y, b0.z, b0.w, b1.x, b1.y, b1.z, b1.w};
            #pragma unroll
            for (int i = 0; i < 8; i++)
                #pragma unroll
                for (int j = 0; j < 8; j++)
                    acc[i][j] = fmaf(ra[i], rb[j], acc[i][j]);
        }
        __syncthreads();
    }

    #pragma unroll
    for (int i = 0; i < 8; i++) {
        size_t row = (size_t)(brow + tr + i);
        float outv[8];
        #pragma unroll
        for (int j = 0; j < 8; j++) {
            float v = acc[i][j];
            int col = bcol + tc + j;
            if (EPI >= 1) v += bias[col];
            if (EPI == 1) v = fmaxf(v, 0.f);
            if (EPI == 2) v += res[row * (size_t)N + col];
            outv[j] = v;
        }
        *(float4*)&C[row * (size_t)N + bcol + tc]     = make_float4(outv[0], outv[1], outv[2], outv[3]);
        *(float4*)&C[row * (size_t)N + bcol + tc + 4] = make_float4(outv[4], outv[5], outv[6], outv[7]);
    }
}

// ---------------- flash attention (fp32, online softmax) ----------------
// Grid (SEQ/64, HEADS, BATCH), 128 threads. BR=BC=64, d=64.
// Layout of Q/K/V: [B, N, H*d] row-major (head h at column offset h*64).
// Scale quirk: logits multiplied by sqrt(d)=8 (folded into Q at load).
#define FA_STR  68
#define FA_SMEM (3 * 64 * FA_STR * 4)

__global__ __launch_bounds__(128) void flash_attn_kernel(const float* __restrict__ Qp,
                                                         const float* __restrict__ Kp,
                                                         const float* __restrict__ Vp,
                                                         float* __restrict__ O)
{
    extern __shared__ float sm[];
    float* Qs = sm;                      // 64 x 68
    float* Ks = sm + 64 * FA_STR;        // 64 x 68 (reused as P after S-compute)
    float* Vs = sm + 2 * 64 * FA_STR;    // 64 x 68

    const int tid = threadIdx.x;
    const int ty  = tid >> 3;   // 0..15
    const int tx  = tid & 7;    // 0..7
    const int b   = blockIdx.z;
    const int h   = blockIdx.y;
    const int q0  = blockIdx.x * 64;
    const size_t base = ((size_t)b * SEQ) * D_MODEL + (size_t)h * HDIM;

    // Load Q tile, pre-scaled by 8
    for (int v = tid; v < 1024; v += 128) {
        int r = v >> 4, c = (v & 15) << 2;
        float4 t = *(const float4*)(Qp + base + (size_t)(q0 + r) * D_MODEL + c);
        t.x *= 8.f; t.y *= 8.f; t.z *= 8.f; t.w *= 8.f;
        *(float4*)&Qs[r * FA_STR + c] = t;
    }

    float m[4], l[4], o[4][8];
    #pragma unroll
    for (int i = 0; i < 4; i++) {
        m[i] = -1e30f; l[i] = 0.f;
        #pragma unroll
        for (int j = 0; j < 8; j++) o[i][j] = 0.f;
    }

    for (int kt = 0; kt < SEQ; kt += 64) {
        __syncthreads();  // prior tile's P/V reads done before overwrite
        for (int v = tid; v < 1024; v += 128) {
            int r = v >> 4, c = (v & 15) << 2;
            *(float4*)&Ks[r * FA_STR + c] = *(const float4*)(Kp + base + (size_t)(kt + r) * D_MODEL + c);
            *(float4*)&Vs[r * FA_STR + c] = *(const float4*)(Vp + base + (size_t)(kt + r) * D_MODEL + c);
        }
        __syncthreads();

        // S = (8*Q) @ K^T   (4 rows x 8 cols per thread)
        float s[4][8];
        #pragma unroll
        for (int i = 0; i < 4; i++)
            #pragma unroll
            for (int j = 0; j < 8; j++) s[i][j] = 0.f;

        #pragma unroll 4
        for (int k = 0; k < 64; k++) {
            float qa[4], kb[8];
            #pragma unroll
            for (int i = 0; i < 4; i++) qa[i] = Qs[(ty + 16 * i) * FA_STR + k];
            #pragma unroll
            for (int j = 0; j < 8; j++) kb[j] = Ks[(tx + 8 * j) * FA_STR + k];
            #pragma unroll
            for (int i = 0; i < 4; i++)
                #pragma unroll
                for (int j = 0; j < 8; j++) s[i][j] = fmaf(qa[i], kb[j], s[i][j]);
        }

        __syncthreads();  // all S-reads of Ks done; safe to overwrite with P

        // Online softmax per row (8 lanes per row: tx = bits 0..2 of lane id)
        #pragma unroll
        for (int i = 0; i < 4; i++) {
            float mx = s[i][0];
            #pragma unroll
            for (int j = 1; j < 8; j++) mx = fmaxf(mx, s[i][j]);
            #pragma unroll
            for (int off = 1; off < 8; off <<= 1)
                mx = fmaxf(mx, __shfl_xor_sync(0xffffffffu, mx, off));
            float mn   = fmaxf(m[i], mx);
            float corr = __expf(m[i] - mn);
            float rs = 0.f;
            #pragma unroll
            for (int j = 0; j < 8; j++) { s[i][j] = __expf(s[i][j] - mn); rs += s[i][j]; }
            #pragma unroll
            for (int off = 1; off < 8; off <<= 1)
                rs += __shfl_xor_sync(0xffffffffu, rs, off);
            l[i] = l[i] * corr + rs;
            m[i] = mn;
            #pragma unroll
            for (int j = 0; j < 8; j++) o[i][j] *= corr;
            #pragma unroll
            for (int j = 0; j < 8; j++) Ks[(ty + 16 * i) * FA_STR + tx + 8 * j] = s[i][j];
        }
        __syncthreads();

        // O += P @ V
        #pragma unroll 4
        for (int c = 0; c < 64; c++) {
            float pr[4], vb[8];
            #pragma unroll
            for (int i = 0; i < 4; i++) pr[i] = Ks[(ty + 16 * i) * FA_STR + c];
            #pragma unroll
            for (int j = 0; j < 8; j++) vb[j] = Vs[c * FA_STR + tx + 8 * j];
            #pragma unroll
            for (int i = 0; i < 4; i++)
                #pragma unroll
                for (int j = 0; j < 8; j++) o[i][j] = fmaf(pr[i], vb[j], o[i][j]);
        }
    }

    #pragma unroll
    for (int i = 0; i < 4; i++) {
        float inv = 1.f / l[i];
        size_t rowoff = base + (size_t)(q0 + ty + 16 * i) * D_MODEL;
        #pragma unroll
        for (int j = 0; j < 8; j++) O[rowoff + tx + 8 * j] = o[i][j] * inv;
    }
}

// ---------------- layernorm (optionally fused residual add) ----------------
__global__ __launch_bounds__(256) void ln_kernel(const float* __restrict__ A,
                                                 const float* __restrict__ Add,
                                                 const float* __restrict__ g,
                                                 const float* __restrict__ bb,
                                                 float* __restrict__ out,
                                                 int useAdd)
{
    __shared__ float red[8];
    const int row = blockIdx.x;
    const size_t off = (size_t)row * D_MODEL;
    const int tid = threadIdx.x;

    float x[4]; float s = 0.f;
    #pragma unroll
    for (int i = 0; i < 4; i++) {
        int c = tid + 256 * i;
        float v = A[off + c];
        if (useAdd) v += Add[off + c];
        x[i] = v; s += v;
    }
    #pragma unroll
    for (int o = 16; o > 0; o >>= 1) s += __shfl_xor_sync(0xffffffffu, s, o);
    if ((tid & 31) == 0) red[tid >> 5] = s;
    __syncthreads();
    float tot = 0.f;
    #pragma unroll
    for (int i = 0; i < 8; i++) tot += red[i];
    const float mean = tot * (1.0f / 1024.0f);

    float vs = 0.f;
    #pragma unroll
    for (int i = 0; i < 4; i++) { float d = x[i] - mean; vs += d * d; }
    #pragma unroll
    for (int o = 16; o > 0; o >>= 1) vs += __shfl_xor_sync(0xffffffffu, vs, o);
    __syncthreads();
    if ((tid & 31) == 0) red[tid >> 5] = vs;
    __syncthreads();
    float vt = 0.f;
    #pragma unroll
    for (int i = 0; i < 8; i++) vt += red[i];
    const float inv = rsqrtf(vt * (1.0f / 1024.0f) + 1e-5f);

    #pragma unroll
    for (int i = 0; i < 4; i++) {
        int c = tid + 256 * i;
        out[off + c] = (x[i] - mean) * inv * g[c] + bb[c];
    }
}

// ---------------- launch ----------------
extern "C" void kernel_launch(void* const* d_in, const int* in_sizes, int n_in,
                              void* d_out, int out_size)
{
    const float* input = (const float*)d_in[0];
    const float* pos   = (const float*)d_in[1];
    const float* Wq    = (const float*)d_in[2];
    const float* Wk    = (const float*)d_in[3];
    const float* Wv    = (const float*)d_in[4];
    const float* W1    = (const float*)d_in[5];
    const float* b1    = (const float*)d_in[6];
    const float* W2    = (const float*)d_in[7];
    const float* b2    = (const float*)d_in[8];
    const float* ln1g  = (const float*)d_in[9];
    const float* ln1b  = (const float*)d_in[10];
    const float* ln2g  = (const float*)d_in[11];
    const float* ln2b  = (const float*)d_in[12];
    float* out = (float*)d_out;

    float *qkin, *Q, *K, *V, *attn, *x1, *ff1, *h;
    cudaGetSymbolAddress((void**)&qkin, g_qkin);
    cudaGetSymbolAddress((void**)&Q,    g_Q);
    cudaGetSymbolAddress((void**)&K,    g_K);
    cudaGetSymbolAddress((void**)&V,    g_V);
    cudaGetSymbolAddress((void**)&attn, g_attn);
    cudaGetSymbolAddress((void**)&x1,   g_x1);
    cudaGetSymbolAddress((void**)&ff1,  g_ff1);
    cudaGetSymbolAddress((void**)&h,    g_h);

    cudaFuncSetAttribute(flash_attn_kernel,
                         cudaFuncAttributeMaxDynamicSharedMemorySize, FA_SMEM);

    // 1) qk_in = input + pos
    {
        int n4 = ROWS * D_MODEL / 4;
        add_kernel<<<(n4 + 255) / 256, 256>>>(input, pos, qkin, n4);
    }

    // 2) Q/K/V projections
    {
        dim3 g1(D_MODEL / 128, ROWS / 128);
        sgemm_kernel<0><<<g1, 256>>>(qkin,  Wq, nullptr, nullptr, Q, ROWS, D_MODEL, D_MODEL);
        sgemm_kernel<0><<<g1, 256>>>(qkin,  Wk, nullptr, nullptr, K, ROWS, D_MODEL, D_MODEL);
        sgemm_kernel<0><<<g1, 256>>>(input, Wv, nullptr, nullptr, V, ROWS, D_MODEL, D_MODEL);
    }

    // 3) attention
    {
        dim3 ga(SEQ / 64, HEADS, BATCH);
        flash_attn_kernel<<<ga, 128, FA_SMEM>>>(Q, K, V, attn);
    }

    // 4) x1 = LN(input + attn)
    ln_kernel<<<ROWS, 256>>>(input, attn, ln1g, ln1b, x1, 1);

    // 5) ff1 = relu(x1 @ W1 + b1)
    {
        dim3 g2(FF_DIM / 128, ROWS / 128);
        sgemm_kernel<1><<<g2, 256>>>(x1, W1, b1, nullptr, ff1, ROWS, FF_DIM, D_MODEL);
    }

    // 6) h = ff1 @ W2 + b2 + x1
    {
        dim3 g3(D_MODEL / 128, ROWS / 128);
        sgemm_kernel<2><<<g3, 256>>>(ff1, W2, b2, x1, h, ROWS, D_MODEL, FF_DIM);
    }

    // 7) out = LN(h)
    ln_kernel<<<ROWS, 256>>>(h, h, ln2g, ln2b, out, 0);
}